// round 1
// baseline (speedup 1.0000x reference)
#include <cuda_runtime.h>
#include <cuda_bf16.h>
#include <stdint.h>

#define D            128
#define TWO_D        256
#define ROWS_PER_BLK 2048
#define THREADS      128   // 4 warps; each warp owns rows (start + warpId + 4*i)

__global__ void zero_out_kernel(float* __restrict__ out, int n) {
    int i = blockIdx.x * blockDim.x + threadIdx.x;
    if (i < n) out[i] = 0.0f;
}

__device__ __forceinline__ void flush_acc(float* __restrict__ out, int b, int lane4,
                                          const float4& a0, const float4& a1) {
    float* p0 = out + (size_t)b * TWO_D + lane4;
    atomicAdd(p0 + 0, a0.x);
    atomicAdd(p0 + 1, a0.y);
    atomicAdd(p0 + 2, a0.z);
    atomicAdd(p0 + 3, a0.w);
    float* p1 = p0 + D;
    atomicAdd(p1 + 0, a1.x);
    atomicAdd(p1 + 1, a1.y);
    atomicAdd(p1 + 2, a1.z);
    atomicAdd(p1 + 3, a1.w);
}

__global__ __launch_bounds__(THREADS)
void pool_kernel(const float* __restrict__ node_rep,
                 const int*   __restrict__ batch_ids,
                 const int*   __restrict__ mol_idx,
                 float*       __restrict__ out,
                 int n_rows) {
    const int warp  = threadIdx.x >> 5;
    const int lane  = threadIdx.x & 31;
    const int lane4 = lane << 2;                 // this lane's d-offset (float4)

    int start = blockIdx.x * ROWS_PER_BLK;
    int end   = start + ROWS_PER_BLK;
    if (end > n_rows) end = n_rows;

    float4 acc0 = make_float4(0.f, 0.f, 0.f, 0.f);
    float4 acc1 = make_float4(0.f, 0.f, 0.f, 0.f);
    int cur_b = -1;

    for (int r = start + warp; r < end; r += 4) {
        // warp-uniform metadata (broadcast LDG)
        const int b = __ldg(batch_ids + r);
        const int m = __ldg(mol_idx   + r);
        // coalesced 512B row read: lane i grabs floats [4i, 4i+4)
        const float4 v = __ldg(reinterpret_cast<const float4*>(node_rep + (size_t)r * D) + lane);

        if (b != cur_b) {                        // rare: graph boundary
            if (cur_b >= 0) {
                flush_acc(out, cur_b, lane4, acc0, acc1);
                acc0 = make_float4(0.f, 0.f, 0.f, 0.f);
                acc1 = make_float4(0.f, 0.f, 0.f, 0.f);
            }
            cur_b = b;
        }
        if (m == 0) {                            // warp-uniform branch, no divergence
            acc0.x += v.x; acc0.y += v.y; acc0.z += v.z; acc0.w += v.w;
        } else {
            acc1.x += v.x; acc1.y += v.y; acc1.z += v.z; acc1.w += v.w;
        }
    }

    if (cur_b >= 0) flush_acc(out, cur_b, lane4, acc0, acc1);
}

extern "C" void kernel_launch(void* const* d_in, const int* in_sizes, int n_in,
                              void* d_out, int out_size) {
    const float* node_rep  = (const float*)d_in[0];
    const int*   batch_ids = (const int*)  d_in[1];
    const int*   mol_idx   = (const int*)  d_in[2];
    float*       out       = (float*)      d_out;

    const int n_rows = in_sizes[1];              // N (batch_ids element count)

    // 1) zero the output (poisoned by harness)
    {
        int threads = 256;
        int blocks  = (out_size + threads - 1) / threads;
        zero_out_kernel<<<blocks, threads>>>(out, out_size);
    }
    // 2) segmented-sum pooling
    {
        int blocks = (n_rows + ROWS_PER_BLK - 1) / ROWS_PER_BLK;
        pool_kernel<<<blocks, THREADS>>>(node_rep, batch_ids, mol_idx, out, n_rows);
    }
}

// round 2
// speedup vs baseline: 1.5140x; 1.5140x over previous
#include <cuda_runtime.h>
#include <cuda_bf16.h>
#include <stdint.h>

#define D             128
#define TWO_D         256
#define WARPS         8
#define THREADS       (WARPS * 32)
#define ROWS_PER_WARP 256
#define ROWS_PER_BLK  (ROWS_PER_WARP * WARPS)   // 2048

__global__ void zero_out_kernel(float4* __restrict__ out, int n4) {
    int i = blockIdx.x * blockDim.x + threadIdx.x;
    if (i < n4) out[i] = make_float4(0.f, 0.f, 0.f, 0.f);
}

__device__ __forceinline__ void flush_acc(float* __restrict__ out, int b, int lane4,
                                          float4& a0, float4& a1) {
    float* p0 = out + (size_t)b * TWO_D + lane4;
    atomicAdd(p0 + 0, a0.x);
    atomicAdd(p0 + 1, a0.y);
    atomicAdd(p0 + 2, a0.z);
    atomicAdd(p0 + 3, a0.w);
    float* p1 = p0 + D;
    atomicAdd(p1 + 0, a1.x);
    atomicAdd(p1 + 1, a1.y);
    atomicAdd(p1 + 2, a1.z);
    atomicAdd(p1 + 3, a1.w);
    a0 = make_float4(0.f, 0.f, 0.f, 0.f);
    a1 = make_float4(0.f, 0.f, 0.f, 0.f);
}

__global__ __launch_bounds__(THREADS)
void pool_kernel(const float* __restrict__ node_rep,
                 const int*   __restrict__ batch_ids,
                 const int*   __restrict__ mol_idx,
                 float*       __restrict__ out,
                 int n_rows) {
    const int warp  = threadIdx.x >> 5;
    const int lane  = threadIdx.x & 31;
    const int lane4 = lane << 2;

    // each warp owns a contiguous 4-aligned chunk of rows
    int cs = blockIdx.x * ROWS_PER_BLK + warp * ROWS_PER_WARP;
    int ce = cs + ROWS_PER_WARP;
    if (cs >= n_rows) return;
    if (ce > n_rows) ce = n_rows;

    float4 acc0 = make_float4(0.f, 0.f, 0.f, 0.f);
    float4 acc1 = make_float4(0.f, 0.f, 0.f, 0.f);
    int cur_b = -1;

    const float4* nr = reinterpret_cast<const float4*>(node_rep);

    int r = cs;
    // unrolled-by-4 main loop: all loads batched up front -> MLP ~6
    for (; r + 3 < ce; r += 4) {
        const int4 bb = __ldg(reinterpret_cast<const int4*>(batch_ids + r));
        const int4 mm = __ldg(reinterpret_cast<const int4*>(mol_idx   + r));
        const float4 v0 = __ldg(nr + (size_t)(r + 0) * (D / 4) + lane);
        const float4 v1 = __ldg(nr + (size_t)(r + 1) * (D / 4) + lane);
        const float4 v2 = __ldg(nr + (size_t)(r + 2) * (D / 4) + lane);
        const float4 v3 = __ldg(nr + (size_t)(r + 3) * (D / 4) + lane);

        // row 0
        if (bb.x != cur_b) { if (cur_b >= 0) flush_acc(out, cur_b, lane4, acc0, acc1); cur_b = bb.x; }
        if (mm.x == 0) { acc0.x += v0.x; acc0.y += v0.y; acc0.z += v0.z; acc0.w += v0.w; }
        else           { acc1.x += v0.x; acc1.y += v0.y; acc1.z += v0.z; acc1.w += v0.w; }
        // row 1
        if (bb.y != cur_b) { flush_acc(out, cur_b, lane4, acc0, acc1); cur_b = bb.y; }
        if (mm.y == 0) { acc0.x += v1.x; acc0.y += v1.y; acc0.z += v1.z; acc0.w += v1.w; }
        else           { acc1.x += v1.x; acc1.y += v1.y; acc1.z += v1.z; acc1.w += v1.w; }
        // row 2
        if (bb.z != cur_b) { flush_acc(out, cur_b, lane4, acc0, acc1); cur_b = bb.z; }
        if (mm.z == 0) { acc0.x += v2.x; acc0.y += v2.y; acc0.z += v2.z; acc0.w += v2.w; }
        else           { acc1.x += v2.x; acc1.y += v2.y; acc1.z += v2.z; acc1.w += v2.w; }
        // row 3
        if (bb.w != cur_b) { flush_acc(out, cur_b, lane4, acc0, acc1); cur_b = bb.w; }
        if (mm.w == 0) { acc0.x += v3.x; acc0.y += v3.y; acc0.z += v3.z; acc0.w += v3.w; }
        else           { acc1.x += v3.x; acc1.y += v3.y; acc1.z += v3.z; acc1.w += v3.w; }
    }
    // remainder (n_rows not multiple of 4)
    for (; r < ce; r++) {
        const int b = __ldg(batch_ids + r);
        const int m = __ldg(mol_idx   + r);
        const float4 v = __ldg(nr + (size_t)r * (D / 4) + lane);
        if (b != cur_b) { if (cur_b >= 0) flush_acc(out, cur_b, lane4, acc0, acc1); cur_b = b; }
        if (m == 0) { acc0.x += v.x; acc0.y += v.y; acc0.z += v.z; acc0.w += v.w; }
        else        { acc1.x += v.x; acc1.y += v.y; acc1.z += v.z; acc1.w += v.w; }
    }

    if (cur_b >= 0) flush_acc(out, cur_b, lane4, acc0, acc1);
}

extern "C" void kernel_launch(void* const* d_in, const int* in_sizes, int n_in,
                              void* d_out, int out_size) {
    const float* node_rep  = (const float*)d_in[0];
    const int*   batch_ids = (const int*)  d_in[1];
    const int*   mol_idx   = (const int*)  d_in[2];
    float*       out       = (float*)      d_out;

    const int n_rows = in_sizes[1];

    {
        int n4 = out_size / 4;
        int threads = 256;
        int blocks  = (n4 + threads - 1) / threads;
        zero_out_kernel<<<blocks, threads>>>((float4*)out, n4);
    }
    {
        int blocks = (n_rows + ROWS_PER_BLK - 1) / ROWS_PER_BLK;
        pool_kernel<<<blocks, THREADS>>>(node_rep, batch_ids, mol_idx, out, n_rows);
    }
}

// round 3
// speedup vs baseline: 1.5220x; 1.0053x over previous
#include <cuda_runtime.h>
#include <cuda_bf16.h>
#include <stdint.h>

#define D             128
#define TWO_D         256
#define WARPS         8
#define THREADS       (WARPS * 32)
#define ROWS_PER_WARP 256
#define ROWS_PER_BLK  (ROWS_PER_WARP * WARPS)   // 2048
#define UNROLL        8

__global__ void zero_out_kernel(float4* __restrict__ out, int n4) {
    int i = blockIdx.x * blockDim.x + threadIdx.x;
    if (i < n4) out[i] = make_float4(0.f, 0.f, 0.f, 0.f);
}

__device__ __forceinline__ void flush_acc(float* __restrict__ out, int b, int lane4,
                                          float4& a0, float4& a1) {
    float* p0 = out + (size_t)b * TWO_D + lane4;
    atomicAdd(p0 + 0, a0.x);
    atomicAdd(p0 + 1, a0.y);
    atomicAdd(p0 + 2, a0.z);
    atomicAdd(p0 + 3, a0.w);
    float* p1 = p0 + D;
    atomicAdd(p1 + 0, a1.x);
    atomicAdd(p1 + 1, a1.y);
    atomicAdd(p1 + 2, a1.z);
    atomicAdd(p1 + 3, a1.w);
    a0 = make_float4(0.f, 0.f, 0.f, 0.f);
    a1 = make_float4(0.f, 0.f, 0.f, 0.f);
}

__global__ __launch_bounds__(THREADS)
void pool_kernel(const float* __restrict__ node_rep,
                 const int*   __restrict__ batch_ids,
                 const int*   __restrict__ mol_idx,
                 float*       __restrict__ out,
                 int n_rows) {
    const int warp  = threadIdx.x >> 5;
    const int lane  = threadIdx.x & 31;
    const int lane4 = lane << 2;

    // each warp owns a contiguous (8-aligned) chunk of rows
    int cs = blockIdx.x * ROWS_PER_BLK + warp * ROWS_PER_WARP;
    int ce = cs + ROWS_PER_WARP;
    if (cs >= n_rows) return;
    if (ce > n_rows) ce = n_rows;

    float4 acc0 = make_float4(0.f, 0.f, 0.f, 0.f);
    float4 acc1 = make_float4(0.f, 0.f, 0.f, 0.f);
    int cur_b = -1;

    const float4* nr = reinterpret_cast<const float4*>(node_rep);

    int r = cs;
    // unrolled-by-8 main loop: all 10 loads batched up front -> MLP ~10
    for (; r + (UNROLL - 1) < ce; r += UNROLL) {
        int   b[UNROLL];
        int   m[UNROLL];
        {
            const int4 bb0 = __ldg(reinterpret_cast<const int4*>(batch_ids + r));
            const int4 bb1 = __ldg(reinterpret_cast<const int4*>(batch_ids + r + 4));
            const int4 mm0 = __ldg(reinterpret_cast<const int4*>(mol_idx   + r));
            const int4 mm1 = __ldg(reinterpret_cast<const int4*>(mol_idx   + r + 4));
            b[0] = bb0.x; b[1] = bb0.y; b[2] = bb0.z; b[3] = bb0.w;
            b[4] = bb1.x; b[5] = bb1.y; b[6] = bb1.z; b[7] = bb1.w;
            m[0] = mm0.x; m[1] = mm0.y; m[2] = mm0.z; m[3] = mm0.w;
            m[4] = mm1.x; m[5] = mm1.y; m[6] = mm1.z; m[7] = mm1.w;
        }
        float4 v[UNROLL];
        #pragma unroll
        for (int u = 0; u < UNROLL; u++)
            v[u] = __ldg(nr + (size_t)(r + u) * (D / 4) + lane);

        #pragma unroll
        for (int u = 0; u < UNROLL; u++) {
            if (b[u] != cur_b) {                 // rare: graph boundary
                if (cur_b >= 0) flush_acc(out, cur_b, lane4, acc0, acc1);
                cur_b = b[u];
            }
            if (m[u] == 0) {                     // warp-uniform, non-divergent
                acc0.x += v[u].x; acc0.y += v[u].y; acc0.z += v[u].z; acc0.w += v[u].w;
            } else {
                acc1.x += v[u].x; acc1.y += v[u].y; acc1.z += v[u].z; acc1.w += v[u].w;
            }
        }
    }
    // remainder
    for (; r < ce; r++) {
        const int b = __ldg(batch_ids + r);
        const int m = __ldg(mol_idx   + r);
        const float4 vv = __ldg(nr + (size_t)r * (D / 4) + lane);
        if (b != cur_b) { if (cur_b >= 0) flush_acc(out, cur_b, lane4, acc0, acc1); cur_b = b; }
        if (m == 0) { acc0.x += vv.x; acc0.y += vv.y; acc0.z += vv.z; acc0.w += vv.w; }
        else        { acc1.x += vv.x; acc1.y += vv.y; acc1.z += vv.z; acc1.w += vv.w; }
    }

    if (cur_b >= 0) flush_acc(out, cur_b, lane4, acc0, acc1);
}

extern "C" void kernel_launch(void* const* d_in, const int* in_sizes, int n_in,
                              void* d_out, int out_size) {
    const float* node_rep  = (const float*)d_in[0];
    const int*   batch_ids = (const int*)  d_in[1];
    const int*   mol_idx   = (const int*)  d_in[2];
    float*       out       = (float*)      d_out;

    const int n_rows = in_sizes[1];

    {
        int n4 = out_size / 4;
        int threads = 256;
        int blocks  = (n4 + threads - 1) / threads;
        zero_out_kernel<<<blocks, threads>>>((float4*)out, n4);
    }
    {
        int blocks = (n_rows + ROWS_PER_BLK - 1) / ROWS_PER_BLK;
        pool_kernel<<<blocks, THREADS>>>(node_rep, batch_ids, mol_idx, out, n_rows);
    }
}

// round 4
// speedup vs baseline: 1.6022x; 1.0527x over previous
#include <cuda_runtime.h>
#include <cuda_bf16.h>
#include <stdint.h>

#define D             128
#define TWO_D         256
#define WARPS         8
#define THREADS       (WARPS * 32)
#define BLOCKS        760              // 152 SMs x 5 blocks/SM -> single full wave
#define TOTAL_WARPS   (BLOCKS * WARPS) // 6080
#define UNROLL        4

__global__ void zero_out_kernel(float4* __restrict__ out, int n4) {
    int i = blockIdx.x * blockDim.x + threadIdx.x;
    if (i < n4) out[i] = make_float4(0.f, 0.f, 0.f, 0.f);
}

__device__ __forceinline__ void flush_acc(float* __restrict__ out, int b, int lane4,
                                          float4& a0, float4& a1) {
    float* p0 = out + (size_t)b * TWO_D + lane4;
    atomicAdd(p0 + 0, a0.x);
    atomicAdd(p0 + 1, a0.y);
    atomicAdd(p0 + 2, a0.z);
    atomicAdd(p0 + 3, a0.w);
    float* p1 = p0 + D;
    atomicAdd(p1 + 0, a1.x);
    atomicAdd(p1 + 1, a1.y);
    atomicAdd(p1 + 2, a1.z);
    atomicAdd(p1 + 3, a1.w);
    a0 = make_float4(0.f, 0.f, 0.f, 0.f);
    a1 = make_float4(0.f, 0.f, 0.f, 0.f);
}

__global__ __launch_bounds__(THREADS, 5)
void pool_kernel(const float* __restrict__ node_rep,
                 const int*   __restrict__ batch_ids,
                 const int*   __restrict__ mol_idx,
                 float*       __restrict__ out,
                 int n_rows,
                 int rows_per_warp) {         // multiple of 4
    const int warp  = threadIdx.x >> 5;
    const int lane  = threadIdx.x & 31;
    const int lane4 = lane << 2;

    // perfectly balanced: one contiguous 4-aligned chunk per warp, single wave
    const int gwarp = blockIdx.x * WARPS + warp;
    int cs = gwarp * rows_per_warp;
    int ce = cs + rows_per_warp;
    if (cs >= n_rows) return;
    if (ce > n_rows) ce = n_rows;

    float4 acc0 = make_float4(0.f, 0.f, 0.f, 0.f);
    float4 acc1 = make_float4(0.f, 0.f, 0.f, 0.f);
    int cur_b = -1;

    const float4* nr = reinterpret_cast<const float4*>(node_rep);

    int r = cs;
    for (; r + (UNROLL - 1) < ce; r += UNROLL) {
        const int4 bb = __ldg(reinterpret_cast<const int4*>(batch_ids + r));
        const int4 mm = __ldg(reinterpret_cast<const int4*>(mol_idx   + r));
        const float4 v0 = __ldg(nr + (size_t)(r + 0) * (D / 4) + lane);
        const float4 v1 = __ldg(nr + (size_t)(r + 1) * (D / 4) + lane);
        const float4 v2 = __ldg(nr + (size_t)(r + 2) * (D / 4) + lane);
        const float4 v3 = __ldg(nr + (size_t)(r + 3) * (D / 4) + lane);

        if (bb.x != cur_b) { if (cur_b >= 0) flush_acc(out, cur_b, lane4, acc0, acc1); cur_b = bb.x; }
        if (mm.x == 0) { acc0.x += v0.x; acc0.y += v0.y; acc0.z += v0.z; acc0.w += v0.w; }
        else           { acc1.x += v0.x; acc1.y += v0.y; acc1.z += v0.z; acc1.w += v0.w; }

        if (bb.y != cur_b) { flush_acc(out, cur_b, lane4, acc0, acc1); cur_b = bb.y; }
        if (mm.y == 0) { acc0.x += v1.x; acc0.y += v1.y; acc0.z += v1.z; acc0.w += v1.w; }
        else           { acc1.x += v1.x; acc1.y += v1.y; acc1.z += v1.z; acc1.w += v1.w; }

        if (bb.z != cur_b) { flush_acc(out, cur_b, lane4, acc0, acc1); cur_b = bb.z; }
        if (mm.z == 0) { acc0.x += v2.x; acc0.y += v2.y; acc0.z += v2.z; acc0.w += v2.w; }
        else           { acc1.x += v2.x; acc1.y += v2.y; acc1.z += v2.z; acc1.w += v2.w; }

        if (bb.w != cur_b) { flush_acc(out, cur_b, lane4, acc0, acc1); cur_b = bb.w; }
        if (mm.w == 0) { acc0.x += v3.x; acc0.y += v3.y; acc0.z += v3.z; acc0.w += v3.w; }
        else           { acc1.x += v3.x; acc1.y += v3.y; acc1.z += v3.z; acc1.w += v3.w; }
    }
    for (; r < ce; r++) {
        const int b = __ldg(batch_ids + r);
        const int m = __ldg(mol_idx   + r);
        const float4 v = __ldg(nr + (size_t)r * (D / 4) + lane);
        if (b != cur_b) { if (cur_b >= 0) flush_acc(out, cur_b, lane4, acc0, acc1); cur_b = b; }
        if (m == 0) { acc0.x += v.x; acc0.y += v.y; acc0.z += v.z; acc0.w += v.w; }
        else        { acc1.x += v.x; acc1.y += v.y; acc1.z += v.z; acc1.w += v.w; }
    }

    if (cur_b >= 0) flush_acc(out, cur_b, lane4, acc0, acc1);
}

extern "C" void kernel_launch(void* const* d_in, const int* in_sizes, int n_in,
                              void* d_out, int out_size) {
    const float* node_rep  = (const float*)d_in[0];
    const int*   batch_ids = (const int*)  d_in[1];
    const int*   mol_idx   = (const int*)  d_in[2];
    float*       out       = (float*)      d_out;

    const int n_rows = in_sizes[1];

    // rows per warp: balanced across TOTAL_WARPS, rounded up to multiple of 4
    int rpw = (n_rows + TOTAL_WARPS - 1) / TOTAL_WARPS;
    rpw = (rpw + 3) & ~3;

    {
        int n4 = out_size / 4;
        int threads = 256;
        int blocks  = (n4 + threads - 1) / threads;
        zero_out_kernel<<<blocks, threads>>>((float4*)out, n4);
    }
    pool_kernel<<<BLOCKS, THREADS>>>(node_rep, batch_ids, mol_idx, out, n_rows, rpw);
}